// round 15
// baseline (speedup 1.0000x reference)
#include <cuda_runtime.h>
#include <cuda_bf16.h>

// SpatialTransformer: 3D trilinear grid-sample, border padding, align_corners=True.
// img [2,1,160,192,224], flow [2,3,160,192,224], out [2,1,160,192,224].
//
// px = (x+flow0+1)*111.5 clamps to 223 (fx=0) for essentially all x>=8 ->
// bilinear on the x=223 border slice. R15: the slice is split into z-HALVES so
// each CTA caches <=89 planes x 197 floats (~70 KB smem) -> 2 CTAs/SM ->
// 64 warps/SM, each iteration holding 6 front-batched float4 flow loads.
// 296 CTAs x 512 threads, one wave. Flows beyond the +-8 z-guard fall back to
// the global compact slice (identical values, ~never taken).
// Phase A: x in [8,224) warp-uniform fast path (4 LDS + 6 FFMA), 8 vox/thread.
// Phase B: x in [0,8) mixed path. SP=197 (197%32==5) spreads banks.

#define DD 160
#define HH 192
#define WW 224
#define HW (HH * WW)
#define NVOX (DD * HH * WW)     // 6,881,280
#define NB 2
#define ROWS (DD * HH)          // 30,720
#define NSLICE (NB * ROWS)      // 61,440

#define SP 197                  // padded smem row stride; 197 % 32 == 5
#define GUARD 8
#define HALF_Z 80
#define HALF_ROWS (HALF_Z * HH)         // 15,360
#define MAX_NZ 89                       // planes cached per CTA (80 + 9)
#define SLAB_BYTES (MAX_NZ * SP * 4)    // 70,132

#define CTAS_PER_HALF 74
#define GRID_MAIN (NB * 2 * CTAS_PER_HALF)   // 296
#define TPB 512
#define GSTRIDE (CTAS_PER_HALF * TPB)        // 37,888

#define HALF_G8 (HALF_ROWS * 27)        // 414,720 groups of 8 vox (x in [8,224))
#define HALF_GB (HALF_ROWS * 2)         // 30,720 groups of 4 vox (x in [0,8))

__device__ float g_bslice[NSLICE];      // compact [b][z*HH+y] = img[b][z][y][223]

__global__ __launch_bounds__(256) void extract_border_kernel(
    const float* __restrict__ img)
{
    int idx = blockIdx.x * blockDim.x + threadIdx.x;
    if (idx >= NSLICE) return;
    int b = idx / ROWS;
    int r = idx - b * ROWS;           // z*HH + y
    int z = r / HH;
    int y = r - z * HH;
    g_bslice[idx] = img[(size_t)b * NVOX + (size_t)z * HW + y * WW + (WW - 1)];
}

// general (non-border) trilinear sample for one voxel
__device__ __forceinline__ float sample_general(
    const float* __restrict__ im, float pxr,
    int y0, int z0, float fy, float fz)
{
    const float px = fmaxf(pxr, 0.0f);          // px < 223 on this path
    const float x0f = floorf(px);
    const float fx = px - x0f;
    const int x0 = (int)x0f;
    const int x1 = min(x0 + 1, WW - 1);
    const int y1 = min(y0 + 1, HH - 1);
    const int z1 = min(z0 + 1, DD - 1);

    const int zb0 = z0 * HW;
    const int zb1 = z1 * HW;
    const int yb0 = y0 * WW;
    const int yb1 = y1 * WW;

    const float c000 = __ldg(im + zb0 + yb0 + x0);
    const float c001 = __ldg(im + zb0 + yb0 + x1);
    const float c010 = __ldg(im + zb0 + yb1 + x0);
    const float c011 = __ldg(im + zb0 + yb1 + x1);
    const float c100 = __ldg(im + zb1 + yb0 + x0);
    const float c101 = __ldg(im + zb1 + yb0 + x1);
    const float c110 = __ldg(im + zb1 + yb1 + x0);
    const float c111 = __ldg(im + zb1 + yb1 + x1);

    const float c00 = c000 + (c001 - c000) * fx;
    const float c01 = c010 + (c011 - c010) * fx;
    const float c10 = c100 + (c101 - c100) * fx;
    const float c11 = c110 + (c111 - c110) * fx;
    const float c0 = c00 + (c01 - c00) * fy;
    const float c1 = c10 + (c11 - c10) * fy;
    return c0 + (c1 - c0) * fz;
}

// border-column bilinear: smem slab if z in cached range, else global slice
__device__ __forceinline__ float sample_border(
    const float* __restrict__ s_slab, const float* __restrict__ gs,
    int zs_lo, int zs_hi, int y0, int z0, float fy, float fz)
{
    const int y1 = min(y0 + 1, HH - 1);
    const int z1 = min(z0 + 1, DD - 1);
    float v00, v01, v10, v11;
    if (z0 >= zs_lo && z1 <= zs_hi) {
        const int r0 = (z0 - zs_lo) * SP + y0;
        const int r1 = (z1 - zs_lo) * SP + y0;
        const int dy = y1 - y0;
        v00 = s_slab[r0];
        v01 = s_slab[r0 + dy];
        v10 = s_slab[r1];
        v11 = s_slab[r1 + dy];
    } else {                                   // Gaussian tail: ~never taken
        v00 = __ldg(gs + z0 * HH + y0);
        v01 = __ldg(gs + z0 * HH + y1);
        v10 = __ldg(gs + z1 * HH + y0);
        v11 = __ldg(gs + z1 * HH + y1);
    }
    const float c0 = v00 + (v01 - v00) * fy;
    const float c1 = v10 + (v11 - v10) * fy;
    return c0 + (c1 - c0) * fz;
}

__global__ __launch_bounds__(TPB, 2) void st3d_kernel(
    const float* __restrict__ img,
    const float* __restrict__ flow,
    float* __restrict__ out)
{
    extern __shared__ float s_slab[];   // [<=MAX_NZ][SP]

    const int tid = threadIdx.x;
    const int cta = blockIdx.x;
    const int b = cta / (2 * CTAS_PER_HALF);
    const int r = cta - b * (2 * CTAS_PER_HALF);
    const int h = r / CTAS_PER_HALF;        // z-half: 0 -> z<80, 1 -> z>=80
    const int c = r - h * CTAS_PER_HALF;

    const int zs_lo = (h == 0) ? 0 : (HALF_Z - GUARD);            // 0 or 72
    const int zs_hi = (h == 0) ? (HALF_Z - 1 + GUARD + 1) : (DD - 1); // 88 or 159
    const int nz = zs_hi - zs_lo + 1;                             // 89 or 88

    const float* gs = g_bslice + b * ROWS;

    // ---- fill smem slab (row-padded) from compact global slice ----
    {
        const float* src = gs + zs_lo * HH;
        for (int idx = tid; idx < nz * HH; idx += TPB) {
            const int zz = idx / HH;
            const int yy = idx - zz * HH;
            s_slab[zz * SP + yy] = __ldg(src + idx);
        }
    }
    __syncthreads();

    const float* fb = flow + (size_t)b * 3 * NVOX;
    const float* im = img + (size_t)b * NVOX;
    float* ob = out + (size_t)b * NVOX;
    const int row_base = h * HALF_ROWS;

    // ====== Phase A: x in [8,224), 8 voxels/thread, warp-uniform fast path ====
    for (int g = c * TPB + tid; g < HALF_G8; g += GSTRIDE) {
        const int row = row_base + g / 27;
        const int i = row * WW + 8 + (g % 27) * 8;   // 16B-aligned
        const int z = row / HH;
        const int y = row - z * HH;
        const int x = i - row * WW;

        // 6 front-batched streaming float4 loads (flow read exactly once)
        const float4 f0lo = __ldcs(reinterpret_cast<const float4*>(fb + i));
        const float4 f0hi = __ldcs(reinterpret_cast<const float4*>(fb + i + 4));
        const float4 f1lo = __ldcs(reinterpret_cast<const float4*>(fb + NVOX + i));
        const float4 f1hi = __ldcs(reinterpret_cast<const float4*>(fb + NVOX + i + 4));
        const float4 f2lo = __ldcs(reinterpret_cast<const float4*>(fb + 2 * NVOX + i));
        const float4 f2hi = __ldcs(reinterpret_cast<const float4*>(fb + 2 * NVOX + i + 4));

        const float f0a[8] = {f0lo.x, f0lo.y, f0lo.z, f0lo.w,
                              f0hi.x, f0hi.y, f0hi.z, f0hi.w};
        const float f1a[8] = {f1lo.x, f1lo.y, f1lo.z, f1lo.w,
                              f1hi.x, f1hi.y, f1hi.z, f1hi.w};
        const float f2a[8] = {f2lo.x, f2lo.y, f2lo.z, f2lo.w,
                              f2hi.x, f2hi.y, f2hi.z, f2hi.w};

        float oa[8];
        #pragma unroll
        for (int k = 0; k < 8; ++k) {
            const float pxr = ((float)(x + k) + f0a[k] + 1.0f) * 111.5f;

            float py = (float)y + f1a[k];
            float pz = (float)z + f2a[k];
            py = fminf(fmaxf(py, 0.0f), (float)(HH - 1));
            pz = fminf(fmaxf(pz, 0.0f), (float)(DD - 1));

            const float y0f = floorf(py);
            const float z0f = floorf(pz);
            const float fy = py - y0f;
            const float fz = pz - z0f;
            const int y0 = (int)y0f;
            const int z0 = (int)z0f;

            if (pxr >= (float)(WW - 1)) {   // uniform-true for x >= 8
                oa[k] = sample_border(s_slab, gs, zs_lo, zs_hi, y0, z0, fy, fz);
            } else {
                oa[k] = sample_general(im, pxr, y0, z0, fy, fz);
            }
        }

        __stcs(reinterpret_cast<float4*>(ob + i),
               make_float4(oa[0], oa[1], oa[2], oa[3]));
        __stcs(reinterpret_cast<float4*>(ob + i + 4),
               make_float4(oa[4], oa[5], oa[6], oa[7]));
    }

    // ====== Phase B: x in [0,8) — mixed path (3.6% of voxels) ================
    for (int g = c * TPB + tid; g < HALF_GB; g += GSTRIDE) {
        const int row = row_base + (g >> 1);
        const int gi = g & 1;
        const int i = row * WW + gi * 4;
        const int z = row / HH;
        const int y = row - z * HH;
        const int x = gi * 4;

        const float4 f0 = __ldcs(reinterpret_cast<const float4*>(fb + i));
        const float4 f1 = __ldcs(reinterpret_cast<const float4*>(fb + NVOX + i));
        const float4 f2 = __ldcs(reinterpret_cast<const float4*>(fb + 2 * NVOX + i));

        const float f0a[4] = {f0.x, f0.y, f0.z, f0.w};
        const float f1a[4] = {f1.x, f1.y, f1.z, f1.w};
        const float f2a[4] = {f2.x, f2.y, f2.z, f2.w};

        float oa[4];
        #pragma unroll
        for (int k = 0; k < 4; ++k) {
            const float pxr = ((float)(x + k) + f0a[k] + 1.0f) * 111.5f;

            float py = (float)y + f1a[k];
            float pz = (float)z + f2a[k];
            py = fminf(fmaxf(py, 0.0f), (float)(HH - 1));
            pz = fminf(fmaxf(pz, 0.0f), (float)(DD - 1));

            const float y0f = floorf(py);
            const float z0f = floorf(pz);
            const float fy = py - y0f;
            const float fz = pz - z0f;
            const int y0 = (int)y0f;
            const int z0 = (int)z0f;

            if (pxr >= (float)(WW - 1)) {
                oa[k] = sample_border(s_slab, gs, zs_lo, zs_hi, y0, z0, fy, fz);
            } else {
                oa[k] = sample_general(im, pxr, y0, z0, fy, fz);
            }
        }

        __stcs(reinterpret_cast<float4*>(ob + i),
               make_float4(oa[0], oa[1], oa[2], oa[3]));
    }
}

extern "C" void kernel_launch(void* const* d_in, const int* in_sizes, int n_in,
                              void* d_out, int out_size)
{
    const float* img  = (const float*)d_in[0];
    const float* flow = (const float*)d_in[1];
    float* out = (float*)d_out;

    cudaFuncSetAttribute(st3d_kernel,
                         cudaFuncAttributeMaxDynamicSharedMemorySize, SLAB_BYTES);

    extract_border_kernel<<<(NSLICE + 255) / 256, 256>>>(img);
    st3d_kernel<<<GRID_MAIN, TPB, SLAB_BYTES>>>(img, flow, out);
}